// round 10
// baseline (speedup 1.0000x reference)
// R9: ldmatrix+cp.async GEMM re-tiled to the PROVEN 81920B dynamic smem
// (R5 ran at this exact size). K-chunk 32, ROWB 80, 2 stages.
#include <cuda_runtime.h>
#include <cuda_bf16.h>
#include <cstdint>
#include <math.h>

#define BB 16
#define RR 1024
#define TT 512
#define DD 1024

// ---------------------------------------------------------------------------
// Scratch (static device arrays — no runtime allocation allowed)
// ---------------------------------------------------------------------------
__device__ __align__(16) unsigned short g_Wrh[DD * DD], g_Wrl[DD * DD];
__device__ __align__(16) unsigned short g_Wqh[DD * DD], g_Wql[DD * DD];
__device__ __align__(16) unsigned short g_Mh[DD * DD],  g_Ml[DD * DD];
__device__ __align__(16) unsigned short g_rfh[BB * RR * DD], g_rfl[BB * RR * DD];
__device__ __align__(16) unsigned short g_qeh[BB * TT * DD], g_qel[BB * TT * DD];
__device__ __align__(16) unsigned short g_qwh[BB * TT * DD], g_qwl[BB * TT * DD];
__device__ __align__(16) unsigned short g_Nth[BB * TT * DD], g_Ntl[BB * TT * DD];
__device__ __align__(16) float g_S[BB * RR * TT];
__device__ __align__(16) float g_H[BB * RR * TT];
__device__ float g_w2[DD];
__device__ float g_c[BB * TT];
__device__ float g_e[BB * TT];
__device__ float g_f[BB * RR];

// ---------------------------------------------------------------------------
// helpers
// ---------------------------------------------------------------------------
__device__ __forceinline__ uint32_t smem_u32(const void* p) {
    uint32_t a;
    asm("{ .reg .u64 t; cvta.to.shared.u64 t, %1; cvt.u32.u64 %0, t; }" : "=r"(a) : "l"(p));
    return a;
}
#define CP_ASYNC16(dst, src) asm volatile(                                        \
    "cp.async.cg.shared.global [%0], [%1], 16;" :: "r"(dst), "l"(src) : "memory")
#define CP_COMMIT() asm volatile("cp.async.commit_group;" ::: "memory")
#define CP_WAIT1() asm volatile("cp.async.wait_group 1;" ::: "memory")
#define CP_WAIT0() asm volatile("cp.async.wait_group 0;" ::: "memory")

#define MMA_BF16(c, a, b)                                                      \
    asm volatile(                                                              \
        "mma.sync.aligned.m16n8k16.row.col.f32.bf16.bf16.f32 "                 \
        "{%0,%1,%2,%3},{%4,%5,%6,%7},{%8,%9},{%0,%1,%2,%3};"                   \
        : "+f"(c[0]), "+f"(c[1]), "+f"(c[2]), "+f"(c[3])                       \
        : "r"(a[0]), "r"(a[1]), "r"(a[2]), "r"(a[3]), "r"(b[0]), "r"(b[1]))

#define LDSM4(r, addr)                                                         \
    asm volatile("ldmatrix.sync.aligned.m8n8.x4.shared.b16 {%0,%1,%2,%3}, [%4];" \
        : "=r"((r)[0]), "=r"((r)[1]), "=r"((r)[2]), "=r"((r)[3]) : "r"(addr))

// ---------------------------------------------------------------------------
// fp32 -> (bf16 hi, bf16 lo) split
// ---------------------------------------------------------------------------
__device__ __forceinline__ void sp(float v, unsigned short& h, unsigned short& l) {
    __nv_bfloat16 bh = __float2bfloat16_rn(v);
    float r = v - __bfloat162float(bh);
    __nv_bfloat16 bl = __float2bfloat16_rn(r);
    h = *reinterpret_cast<unsigned short*>(&bh);
    l = *reinterpret_cast<unsigned short*>(&bl);
}

__global__ void split_kernel(const float4* __restrict__ x,
                             ushort4* __restrict__ h, ushort4* __restrict__ l, int n4) {
    int i = blockIdx.x * blockDim.x + threadIdx.x;
    if (i >= n4) return;
    float4 v = x[i];
    ushort4 hh, ll;
    sp(v.x, hh.x, ll.x); sp(v.y, hh.y, ll.y);
    sp(v.z, hh.z, ll.z); sp(v.w, hh.w, ll.w);
    h[i] = hh; l[i] = ll;
}

__global__ void split_qw_kernel(const float4* __restrict__ qe, const float* __restrict__ Ws3,
                                ushort4* __restrict__ h, ushort4* __restrict__ l, int n4) {
    int i = blockIdx.x * blockDim.x + threadIdx.x;
    if (i >= n4) return;
    float4 v = qe[i];
    int d0 = (i * 4) & (DD - 1);
    float4 w = *(const float4*)&Ws3[d0];
    v.x *= w.x; v.y *= w.y; v.z *= w.z; v.w *= w.w;
    ushort4 hh, ll;
    sp(v.x, hh.x, ll.x); sp(v.y, hh.y, ll.y);
    sp(v.z, hh.z, ll.z); sp(v.w, hh.w, ll.w);
    h[i] = hh; l[i] = ll;
}

// ---------------------------------------------------------------------------
// ldmatrix + cp.async 3-pass split-bf16 NT GEMM (legacy tensor path).
//   C[M,N] = A[M,K]*B[N,K]^T as Ah*Bh + Ah*Bl + Al*Bh, fp32 accum.
// CTA 128x128, 8 warps (2x4), warp tile 64x32. K chunk 32, 2-stage cp.async.
// Smem rows: 64B data + 16B pad (80B = 20 words):
//   8 consecutive rows hit banks {0,20,8,28,16,4,24,12}*..+3 -> all 32 banks,
//   conflict-free for both ldmatrix phases and quarter-warp cp.async stores.
// mode 0: fp32 C ; mode 1: split bf16 (Ch, Cl).
// ---------------------------------------------------------------------------
#define ROWB 80
#define TILE_B (128 * ROWB)          // 10240
#define STAGE_B (4 * TILE_B)         // 40960
#define SMEM_G (2 * STAGE_B)         // 81920  (== R5's proven size)

__global__ __launch_bounds__(256, 1)
void gemm3_ldsm(const unsigned short* __restrict__ Ah, const unsigned short* __restrict__ Al,
                const unsigned short* __restrict__ Bh, const unsigned short* __restrict__ Bl,
                float* __restrict__ Cf, unsigned short* __restrict__ Ch,
                unsigned short* __restrict__ Cl,
                int Ndim, int K,
                long long sA, long long sB, long long sC, int mode) {
    extern __shared__ char smc[];
    const uint32_t sb = smem_u32(smc);
    const int tid = threadIdx.x, lane = tid & 31, warp = tid >> 5;
    const int g = lane >> 2, tq = lane & 3;
    const int wm = warp & 1, wn = warp >> 1;
    const int row0 = blockIdx.y * 128, col0 = blockIdx.x * 128;
    const long long z = blockIdx.z;

    const unsigned short* pA[2] = {Ah + z * sA, Al + z * sA};
    const unsigned short* pB[2] = {Bh + z * sB, Bl + z * sB};

    float c[4][4][4];
    #pragma unroll
    for (int i = 0; i < 4; i++)
        #pragma unroll
        for (int j = 0; j < 4; j++)
            #pragma unroll
            for (int q = 0; q < 4; q++) c[i][j][q] = 0.f;

    // ---- cp.async one K-chunk (32 elems = 64B/row) into stage cc&1 ----
    // Per tile: 128 rows x 4 groups of 16B. Quarter-warp = same group,
    // 8 consecutive rows -> conflict-free stores.
    auto load_chunk = [&](int cc) {
        const uint32_t st = sb + (uint32_t)(cc & 1) * STAGE_B;
        const int kc = cc << 5;
        #pragma unroll
        for (int it = 0; it < 8; it++) {
            const int f = tid + it * 256;       // 0..2047
            const int tau = f >> 9;             // 0:Ah 1:Al 2:Bh 3:Bl
            const int w = f & 511;              // within tile
            const int gg = (w >> 3) & 3;        // 16B group 0..3
            const int r  = (w & 7) | ((w >> 5) << 3);   // row 0..127
            const unsigned short* src =
                (tau < 2) ? pA[tau] + (size_t)(row0 + r) * K + kc + gg * 8
                          : pB[tau - 2] + (size_t)(col0 + r) * K + kc + gg * 8;
            const uint32_t dst = st + (uint32_t)tau * TILE_B + (uint32_t)(r * ROWB + gg * 16);
            CP_ASYNC16(dst, src);
        }
        CP_COMMIT();
    };

    const int NC = K >> 5;
    load_chunk(0);
    if (NC > 1) load_chunk(1);

    // per-lane ldmatrix offsets within a tile
    const uint32_t aoff = (uint32_t)((wm * 64 + (lane & 15)) * ROWB + (lane >> 4) * 16);
    const uint32_t boff = (uint32_t)((wn * 32 + (lane & 15)) * ROWB + (lane >> 4) * 16);

    for (int cc = 0; cc < NC; cc++) {
        if (cc + 1 < NC) CP_WAIT1(); else CP_WAIT0();
        __syncthreads();

        const uint32_t st = sb + (uint32_t)(cc & 1) * STAGE_B;
        #pragma unroll
        for (int ks = 0; ks < 2; ks++) {
            const uint32_t kso = (uint32_t)(ks * 32);   // k16 step: +32B
            uint32_t ah[4][4], al[4][4], bh4[2][4], bl4[2][4];
            #pragma unroll
            for (int i = 0; i < 4; i++) {
                LDSM4(ah[i], st + 0 * TILE_B + aoff + (uint32_t)(i * 16 * ROWB) + kso);
                LDSM4(al[i], st + 1 * TILE_B + aoff + (uint32_t)(i * 16 * ROWB) + kso);
            }
            #pragma unroll
            for (int j = 0; j < 2; j++) {
                LDSM4(bh4[j], st + 2 * TILE_B + boff + (uint32_t)(j * 16 * ROWB) + kso);
                LDSM4(bl4[j], st + 3 * TILE_B + boff + (uint32_t)(j * 16 * ROWB) + kso);
            }
            #pragma unroll
            for (int i = 0; i < 4; i++)
                #pragma unroll
                for (int jj = 0; jj < 4; jj++) {
                    // n8 block jj: x4 regs {r0,r2} = rows 0-7, {r1,r3} = rows 8-15
                    uint32_t bhf[2] = {bh4[jj >> 1][jj & 1], bh4[jj >> 1][(jj & 1) + 2]};
                    uint32_t blf[2] = {bl4[jj >> 1][jj & 1], bl4[jj >> 1][(jj & 1) + 2]};
                    MMA_BF16(c[i][jj], ah[i], bhf);
                    MMA_BF16(c[i][jj], ah[i], blf);
                    MMA_BF16(c[i][jj], al[i], bhf);
                }
        }
        __syncthreads();
        if (cc + 2 < NC) load_chunk(cc + 2);
    }

    // ---- epilogue: direct from accumulators ----
    #pragma unroll
    for (int i = 0; i < 4; i++)
        #pragma unroll
        for (int j = 0; j < 4; j++) {
            int r  = row0 + wm * 64 + i * 16 + g;
            int cn = col0 + wn * 32 + j * 8 + tq * 2;
            if (mode == 0) {
                float* P = Cf + z * sC;
                *(float2*)&P[(size_t)r * Ndim + cn] = make_float2(c[i][j][0], c[i][j][1]);
                *(float2*)&P[(size_t)(r + 8) * Ndim + cn] = make_float2(c[i][j][2], c[i][j][3]);
            } else {
                unsigned short* PH = Ch + z * sC;
                unsigned short* PL = Cl + z * sC;
                unsigned short h0, l0, h1, l1;
                sp(c[i][j][0], h0, l0); sp(c[i][j][1], h1, l1);
                *(ushort2*)&PH[(size_t)r * Ndim + cn] = make_ushort2(h0, h1);
                *(ushort2*)&PL[(size_t)r * Ndim + cn] = make_ushort2(l0, l1);
                sp(c[i][j][2], h0, l0); sp(c[i][j][3], h1, l1);
                *(ushort2*)&PH[(size_t)(r + 8) * Ndim + cn] = make_ushort2(h0, h1);
                *(ushort2*)&PL[(size_t)(r + 8) * Ndim + cn] = make_ushort2(l0, l1);
            }
        }
}

// ---------------------------------------------------------------------------
// Small fp32 helper kernels
// ---------------------------------------------------------------------------
__global__ void w2_kernel(const float* __restrict__ Wq, const float* __restrict__ br,
                          float* __restrict__ w2) {
    int warp = (blockIdx.x * blockDim.x + threadIdx.x) >> 5;
    int lane = threadIdx.x & 31;
    if (warp >= DD) return;
    const float* row = Wq + (size_t)warp * DD;
    float s = 0.f;
    for (int h = lane; h < DD; h += 32) s += row[h] * br[h];
    #pragma unroll
    for (int o = 16; o; o >>= 1) s += __shfl_xor_sync(0xffffffffu, s, o);
    if (lane == 0) w2[warp] = s;
}

__global__ void ce_kernel(const float* __restrict__ qe, const float* __restrict__ w2,
                          const float* __restrict__ Ws2,
                          float* __restrict__ c, float* __restrict__ e) {
    int warp = (blockIdx.x * blockDim.x + threadIdx.x) >> 5;
    int lane = threadIdx.x & 31;
    if (warp >= BB * TT) return;
    const float* row = qe + (size_t)warp * DD;
    float sc = 0.f, se = 0.f;
    for (int d = lane; d < DD; d += 32) {
        float q = row[d];
        sc += q * w2[d];
        se += q * Ws2[d];
    }
    #pragma unroll
    for (int o = 16; o; o >>= 1) {
        sc += __shfl_xor_sync(0xffffffffu, sc, o);
        se += __shfl_xor_sync(0xffffffffu, se, o);
    }
    if (lane == 0) { c[warp] = sc; e[warp] = se; }
}

__global__ void f_kernel(const float* __restrict__ rf, const float* __restrict__ Ws1,
                         float* __restrict__ f) {
    int warp = (blockIdx.x * blockDim.x + threadIdx.x) >> 5;
    int lane = threadIdx.x & 31;
    if (warp >= BB * RR) return;
    const float* row = rf + (size_t)warp * DD;
    float s = 0.f;
    for (int d = lane; d < DD; d += 32) s += row[d] * Ws1[d];
    #pragma unroll
    for (int o = 16; o; o >>= 1) s += __shfl_xor_sync(0xffffffffu, s, o);
    if (lane == 0) f[warp] = s;
}

__global__ __launch_bounds__(256)
void finalize_kernel(const float* __restrict__ S, const float* __restrict__ Hm,
                     const float* __restrict__ c, const float* __restrict__ e,
                     const float* __restrict__ f, const float* __restrict__ bs,
                     float* __restrict__ out) {
    const int idx = blockIdx.x;
    const int b   = idx >> 10;
    const float* Srow = S  + (size_t)idx * TT;
    const float* Hrow = Hm + (size_t)idx * TT;
    const float* cb   = c + b * TT;
    const float* eb   = e + b * TT;
    const int tid = threadIdx.x;

    __shared__ float red[8];
    __shared__ float rs[8], ra[8];

    float m = -1e30f;
    for (int i = tid; i < TT; i += 256) m = fmaxf(m, Srow[i] + cb[i]);
    #pragma unroll
    for (int o = 16; o; o >>= 1) m = fmaxf(m, __shfl_xor_sync(0xffffffffu, m, o));
    if ((tid & 31) == 0) red[tid >> 5] = m;
    __syncthreads();
    if (tid < 8) {
        float v = red[tid];
        #pragma unroll
        for (int o = 4; o; o >>= 1) v = fmaxf(v, __shfl_xor_sync(0xffu, v, o));
        if (tid == 0) red[0] = v;
    }
    __syncthreads();
    m = red[0];

    float sum = 0.f, acc = 0.f;
    for (int i = tid; i < TT; i += 256) {
        float w = expf(Srow[i] + cb[i] - m);
        sum += w;
        acc += w * (eb[i] + Hrow[i]);
    }
    #pragma unroll
    for (int o = 16; o; o >>= 1) {
        sum += __shfl_xor_sync(0xffffffffu, sum, o);
        acc += __shfl_xor_sync(0xffffffffu, acc, o);
    }
    if ((tid & 31) == 0) { rs[tid >> 5] = sum; ra[tid >> 5] = acc; }
    __syncthreads();
    if (tid == 0) {
        float s = 0.f, a = 0.f;
        #pragma unroll
        for (int w = 0; w < 8; w++) { s += rs[w]; a += ra[w]; }
        out[idx] = a / s + f[idx] + bs[0];
    }
}

// ---------------------------------------------------------------------------
// Launch
// ---------------------------------------------------------------------------
extern "C" void kernel_launch(void* const* d_in, const int* in_sizes, int n_in,
                              void* d_out, int out_size) {
    const float* rf = (const float*)d_in[0];
    const float* qe = (const float*)d_in[1];
    const float* Wr = (const float*)d_in[2];
    const float* br = (const float*)d_in[3];
    const float* Wq = (const float*)d_in[4];
    // d_in[5] = bq: softmax-invariant, provably drops out
    const float* Ws = (const float*)d_in[6];
    const float* bs = (const float*)d_in[7];
    float* out = (float*)d_out;

    unsigned short *wrh, *wrl, *wqh, *wql, *mh, *ml, *rfh, *rfl, *qeh, *qel,
                   *qwh, *qwl, *nth, *ntl;
    float *gS, *gH, *gw2, *gc, *ge, *gf;
    cudaGetSymbolAddress((void**)&wrh, g_Wrh); cudaGetSymbolAddress((void**)&wrl, g_Wrl);
    cudaGetSymbolAddress((void**)&wqh, g_Wqh); cudaGetSymbolAddress((void**)&wql, g_Wql);
    cudaGetSymbolAddress((void**)&mh,  g_Mh);  cudaGetSymbolAddress((void**)&ml,  g_Ml);
    cudaGetSymbolAddress((void**)&rfh, g_rfh); cudaGetSymbolAddress((void**)&rfl, g_rfl);
    cudaGetSymbolAddress((void**)&qeh, g_qeh); cudaGetSymbolAddress((void**)&qel, g_qel);
    cudaGetSymbolAddress((void**)&qwh, g_qwh); cudaGetSymbolAddress((void**)&qwl, g_qwl);
    cudaGetSymbolAddress((void**)&nth, g_Nth); cudaGetSymbolAddress((void**)&ntl, g_Ntl);
    cudaGetSymbolAddress((void**)&gS,  g_S);   cudaGetSymbolAddress((void**)&gH,  g_H);
    cudaGetSymbolAddress((void**)&gw2, g_w2);  cudaGetSymbolAddress((void**)&gc,  g_c);
    cudaGetSymbolAddress((void**)&ge,  g_e);   cudaGetSymbolAddress((void**)&gf,  g_f);

    cudaFuncSetAttribute(gemm3_ldsm, cudaFuncAttributeMaxDynamicSharedMemorySize, SMEM_G);

    // ---- splits ----
    {
        int n4 = DD * DD / 4;
        split_kernel<<<(n4 + 255) / 256, 256>>>((const float4*)Wr, (ushort4*)wrh, (ushort4*)wrl, n4);
        split_kernel<<<(n4 + 255) / 256, 256>>>((const float4*)Wq, (ushort4*)wqh, (ushort4*)wql, n4);
    }
    {
        int n4 = BB * RR * DD / 4;
        split_kernel<<<(n4 + 255) / 256, 256>>>((const float4*)rf, (ushort4*)rfh, (ushort4*)rfl, n4);
    }
    {
        int n4 = BB * TT * DD / 4;
        split_kernel<<<(n4 + 255) / 256, 256>>>((const float4*)qe, (ushort4*)qeh, (ushort4*)qel, n4);
        split_qw_kernel<<<(n4 + 255) / 256, 256>>>((const float4*)qe, Ws + 2 * DD,
                                                   (ushort4*)qwh, (ushort4*)qwl, n4);
    }

    // ---- small bias/vector terms (fp32) ----
    w2_kernel<<<(DD * 32 + 255) / 256, 256>>>(Wq, br, gw2);
    ce_kernel<<<(BB * TT * 32 + 255) / 256, 256>>>(qe, gw2, Ws + DD, gc, ge);
    f_kernel<<<(BB * RR * 32 + 255) / 256, 256>>>(rf, Ws, gf);

    // ---- M = Wr @ Wq^T -> split bf16 (mode 1) ----
    gemm3_ldsm<<<dim3(DD / 128, DD / 128, 1), 256, SMEM_G>>>(
        wrh, wrl, wqh, wql, nullptr, mh, ml, DD, DD, 0, 0, 0, 1);

    // ---- Nt[b] = qe[b] @ M^T -> split bf16 [T,D] ----
    gemm3_ldsm<<<dim3(DD / 128, TT / 128, BB), 256, SMEM_G>>>(
        qeh, qel, mh, ml, nullptr, nth, ntl, DD, DD,
        (long long)TT * DD, 0, (long long)TT * DD, 1);

    // ---- S[b] = rf[b] @ Nt[b]^T -> fp32 [R,T] ----
    gemm3_ldsm<<<dim3(TT / 128, RR / 128, BB), 256, SMEM_G>>>(
        rfh, rfl, nth, ntl, gS, nullptr, nullptr, TT, DD,
        (long long)RR * DD, (long long)TT * DD, (long long)RR * TT, 0);

    // ---- H[b] = rf[b] @ qw[b]^T -> fp32 [R,T] ----
    gemm3_ldsm<<<dim3(TT / 128, RR / 128, BB), 256, SMEM_G>>>(
        rfh, rfl, qwh, qwl, gH, nullptr, nullptr, TT, DD,
        (long long)RR * DD, (long long)TT * DD, (long long)RR * TT, 0);

    // ---- softmax + weighted reduce + bias terms ----
    finalize_kernel<<<BB * RR, 256>>>(gS, gH, gc, ge, gf, bs, out);
}